// round 11
// baseline (speedup 1.0000x reference)
#include <cuda_runtime.h>
#include <cuda_fp16.h>
#include <stdint.h>

namespace {

constexpr int M  = 32;
constexpr int N  = 11008;
constexpr int K  = 4096;
constexpr int NT = 32;               // output channels per CTA -> grid = 344
constexpr int KC = 128;              // K elems per staged chunk
constexpr int NITER = K / KC;        // 32
constexpr int NKS = K / 16;          // 256 k16 steps
constexpr int WTS = 136;             // padded stride in halves (17x16B): conflict-free ldsm
constexpr int WT_HALVES = NT * WTS;  // 4352 halves per buffer

// Pre-packed fp16 A fragments: [ks][mt][lane][4 u32]  (256 KB, L2-resident)
__device__ __align__(16) uint32_t g_afrag[NKS * 2 * 32 * 4];

__device__ __forceinline__ uint32_t h2_u32(__half2 h) {
    return *reinterpret_cast<uint32_t*>(&h);
}

__global__ void prep_afrag(const float* __restrict__ x) {
    const int idx  = blockIdx.x * blockDim.x + threadIdx.x;  // 0..16383
    const int lane = idx & 31;
    const int mt   = (idx >> 5) & 1;
    const int ks   = idx >> 6;
    const int gm   = lane >> 2;
    const int fk   = (lane & 3) * 2;
    const int r0   = mt * 16 + gm;
    const int r1   = r0 + 8;
    const int c0   = ks * 16 + fk;

    uint32_t u0 = h2_u32(__floats2half2_rn(x[(size_t)r0 * K + c0],     x[(size_t)r0 * K + c0 + 1]));
    uint32_t u1 = h2_u32(__floats2half2_rn(x[(size_t)r1 * K + c0],     x[(size_t)r1 * K + c0 + 1]));
    uint32_t u2 = h2_u32(__floats2half2_rn(x[(size_t)r0 * K + c0 + 8], x[(size_t)r0 * K + c0 + 9]));
    uint32_t u3 = h2_u32(__floats2half2_rn(x[(size_t)r1 * K + c0 + 8], x[(size_t)r1 * K + c0 + 9]));

    *reinterpret_cast<uint4*>(&g_afrag[(size_t)((ks * 2 + mt) * 32 + lane) * 4]) =
        make_uint4(u0, u1, u2, u3);
}

__device__ __forceinline__ void ldsm2(uint32_t r[2], uint32_t a) {
    asm volatile("ldmatrix.sync.aligned.m8n8.x2.shared.b16 {%0,%1}, [%2];"
                 : "=r"(r[0]), "=r"(r[1]) : "r"(a));
}
__device__ __forceinline__ void mma16816(float c[4], const uint32_t a[4], const uint32_t b[2]) {
    asm volatile(
        "mma.sync.aligned.m16n8k16.row.col.f32.f16.f16.f32 "
        "{%0,%1,%2,%3}, {%4,%5,%6,%7}, {%8,%9}, {%0,%1,%2,%3};"
        : "+f"(c[0]), "+f"(c[1]), "+f"(c[2]), "+f"(c[3])
        : "r"(a[0]), "r"(a[1]), "r"(a[2]), "r"(a[3]), "r"(b[0]), "r"(b[1]));
}

__global__ void __launch_bounds__(128, 4)
qlinear_kernel(const uint32_t* __restrict__ qw,
               const float* __restrict__ scales, const float* __restrict__ bias,
               float* __restrict__ out)
{
    __shared__ __half smw[2][WT_HALVES];

    const int tid  = threadIdx.x;
    const int lane = tid & 31;
    const int wn   = tid >> 5;           // warp = n8 slot (0..3)
    const int o0   = blockIdx.x * NT;

    // ---- uniform dtype probe on qweight words: 0 = int32, 1 = float32 ----
    int mode;
    {
        uint32_t all_int = 1u;
#pragma unroll
        for (int i = 0; i < 8; ++i) {
            uint32_t w = __ldg(qw + i);
            all_int &= ((w + 128u) < 256u) ? 1u : 0u;
        }
        mode = all_int ? 0 : 1;
    }

    // ---- weight staging: 32 rows x 128 words, 8 x 16B chunks per thread ----
    // chunk g = p*128 + tid : row = g>>5 (32 chunks/row), col4 = g&31
    uint4 wreg[8];
    auto ldw = [&](int it) {
        const int kc = it * KC;
#pragma unroll
        for (int p = 0; p < 8; ++p) {
            const int g = p * 128 + tid;
            wreg[p] = *reinterpret_cast<const uint4*>(
                qw + (size_t)(o0 + (g >> 5)) * K + kc + (g & 31) * 4);
        }
    };
    auto stw = [&](int buf) {
        __half* wt = smw[buf];
#pragma unroll
        for (int p = 0; p < 8; ++p) {
            const int g = p * 128 + tid;
            float f0, f1, f2, f3;
            if (mode == 0) {
                f0 = (float)(int)wreg[p].x; f1 = (float)(int)wreg[p].y;
                f2 = (float)(int)wreg[p].z; f3 = (float)(int)wreg[p].w;
            } else {
                f0 = __uint_as_float(wreg[p].x); f1 = __uint_as_float(wreg[p].y);
                f2 = __uint_as_float(wreg[p].z); f3 = __uint_as_float(wreg[p].w);
            }
            *reinterpret_cast<uint2*>(wt + (g >> 5) * WTS + (g & 31) * 4) =
                make_uint2(h2_u32(__floats2half2_rn(f0, f1)),
                           h2_u32(__floats2half2_rn(f2, f3)));
        }
    };

    // ---- B ldmatrix address (n8 x k16 per warp) ----
    const int laneB = lane & 15;
    const int rowB  = laneB & 7;
    const int colB  = (laneB >> 3) * 8;
    const uint32_t smw0 = (uint32_t)__cvta_generic_to_shared(&smw[0][0]);
    const uint32_t smw1 = (uint32_t)__cvta_generic_to_shared(&smw[1][0]);
    const uint32_t boff = (uint32_t)((wn * 8 + rowB) * WTS + colB) * 2;

    // ---- A fragment stream from g_afrag (L2-resident, coalesced) ----
    const uint4* afr = reinterpret_cast<const uint4*>(g_afrag) + lane;
    auto lda = [&](uint32_t a[2][4], int ks) {
        uint4 v0 = __ldg(afr + (size_t)(ks * 2) * 32);
        uint4 v1 = __ldg(afr + (size_t)(ks * 2 + 1) * 32);
        a[0][0] = v0.x; a[0][1] = v0.y; a[0][2] = v0.z; a[0][3] = v0.w;
        a[1][0] = v1.x; a[1][1] = v1.y; a[1][2] = v1.z; a[1][3] = v1.w;
    };

    float acc[2][4];
#pragma unroll
    for (int i = 0; i < 2; ++i)
#pragma unroll
        for (int e = 0; e < 4; ++e) acc[i][e] = 0.f;

    uint32_t ac[2][4], an[2][4];

    // ---- prologue ----
    ldw(0);
    stw(0);
    lda(ac, 0);
    __syncthreads();

    // ---- mainloop: r3 cadence, but A from global and tiny independent CTAs ----
    for (int it = 0; it < NITER; ++it) {
        const bool more = (it + 1 < NITER);
        if (more) ldw(it + 1);

        const uint32_t base = (it & 1) ? smw1 : smw0;
#pragma unroll
        for (int s = 0; s < 8; ++s) {
            const int ks = it * 8 + s;
            if (ks + 1 < NKS) lda(an, ks + 1);
            uint32_t b[2];
            ldsm2(b, base + boff + (uint32_t)s * 32);
            mma16816(acc[0], ac[0], b);
            mma16816(acc[1], ac[1], b);
#pragma unroll
            for (int i = 0; i < 2; ++i)
#pragma unroll
                for (int e = 0; e < 4; ++e) ac[i][e] = an[i][e];
        }

        if (more) stw((it + 1) & 1);
        __syncthreads();
    }

    // ---- epilogue: warp owns full-K n8 slot; no reduction needed ----
    const int gm = lane >> 2;
    const int gn = (lane & 3) * 2;
    const int o  = o0 + wn * 8 + gn;
    const float s0 = scales[o];
    const float s1 = scales[o + 1];
    const float b0 = bias[o];
    const float b1 = bias[o + 1];
#pragma unroll
    for (int mt = 0; mt < 2; ++mt) {
        const float* c = acc[mt];
        const int r0 = mt * 16 + gm;
        float2 v0, v1;
        v0.x = __half2float(__float2half_rn(c[0] * s0 + b0));
        v0.y = __half2float(__float2half_rn(c[1] * s1 + b1));
        v1.x = __half2float(__float2half_rn(c[2] * s0 + b0));
        v1.y = __half2float(__float2half_rn(c[3] * s1 + b1));
        *reinterpret_cast<float2*>(out + (size_t)r0 * N + o) = v0;
        *reinterpret_cast<float2*>(out + (size_t)(r0 + 8) * N + o) = v1;
    }
}

} // anonymous namespace

extern "C" void kernel_launch(void* const* d_in, const int* in_sizes, int n_in,
                              void* d_out, int out_size) {
    const float*    x  = reinterpret_cast<const float*>(d_in[0]);
    const uint32_t* qw = reinterpret_cast<const uint32_t*>(d_in[1]);
    const float*    sc = reinterpret_cast<const float*>(d_in[2]);
    const float*    bi = reinterpret_cast<const float*>(d_in[3]);
    float*          o  = reinterpret_cast<float*>(d_out);

    prep_afrag<<<(NKS * 2 * 32) / 256, 256>>>(x);
    qlinear_kernel<<<N / NT, 128>>>(qw, sc, bi, o);
}

// round 13
// speedup vs baseline: 2.1926x; 2.1926x over previous
#include <cuda_runtime.h>
#include <cuda_fp16.h>
#include <stdint.h>

namespace {

constexpr int M  = 32;
constexpr int N  = 11008;
constexpr int K  = 4096;
constexpr int NT = 64;                // output channels per CTA
constexpr int NSPLIT = 4;             // K split across CTAs
constexpr int KSEG = K / NSPLIT;      // 1024
constexpr int KC = 64;                // K elems per staged chunk
constexpr int NITER = KSEG / KC;      // 16
constexpr int WTS = 72;               // padded stride in halves (9x16B rows): conflict-free ldsm
constexpr int WT_HALVES = NT * WTS;   // 4608
constexpr int XT_HALVES = M  * WTS;   // 2304
constexpr int BUF_HALVES = WT_HALVES + XT_HALVES;  // 6912 (13824 B per buffer)

// raw fp32 partials per k-split (5.6 MB, written fully each run)
__device__ float g_partial[NSPLIT][M][N];

__device__ __forceinline__ void ldsm4(uint32_t r[4], uint32_t a) {
    asm volatile("ldmatrix.sync.aligned.m8n8.x4.shared.b16 {%0,%1,%2,%3}, [%4];"
                 : "=r"(r[0]), "=r"(r[1]), "=r"(r[2]), "=r"(r[3]) : "r"(a));
}
__device__ __forceinline__ void ldsm2(uint32_t r[2], uint32_t a) {
    asm volatile("ldmatrix.sync.aligned.m8n8.x2.shared.b16 {%0,%1}, [%2];"
                 : "=r"(r[0]), "=r"(r[1]) : "r"(a));
}
__device__ __forceinline__ void mma16816(float c[4], const uint32_t a[4], const uint32_t b[2]) {
    asm volatile(
        "mma.sync.aligned.m16n8k16.row.col.f32.f16.f16.f32 "
        "{%0,%1,%2,%3}, {%4,%5,%6,%7}, {%8,%9}, {%0,%1,%2,%3};"
        : "+f"(c[0]), "+f"(c[1]), "+f"(c[2]), "+f"(c[3])
        : "r"(a[0]), "r"(a[1]), "r"(a[2]), "r"(a[3]), "r"(b[0]), "r"(b[1]));
}
__device__ __forceinline__ uint32_t h2_u32(__half2 h) {
    return *reinterpret_cast<uint32_t*>(&h);
}

__global__ void __launch_bounds__(128, 4)
qlinear_main(const float* __restrict__ x, const uint32_t* __restrict__ qw)
{
    __shared__ __half smw[2][BUF_HALVES];

    const int tid  = threadIdx.x;
    const int lane = tid & 31;
    const int wn   = tid >> 5;               // warp = n16 slot (0..3)
    const int o0   = blockIdx.x * NT;
    const int spl  = blockIdx.y;
    const int k0   = spl * KSEG;

    // ---- uniform dtype probe on qweight words: 0 = int32, 1 = float32 ----
    int mode;
    {
        uint32_t all_int = 1u;
#pragma unroll
        for (int i = 0; i < 8; ++i) {
            uint32_t w = __ldg(qw + i);
            all_int &= ((w + 128u) < 256u) ? 1u : 0u;
        }
        mode = all_int ? 0 : 1;
    }

    // per-thread granule map: 16B chunks, 16 chunks per 64-word row
    const int rb  = tid >> 4;                // row base 0..7
    const int c16 = tid & 15;
    const uint32_t* wsrc = qw + (size_t)(o0 + rb) * K + k0 + c16 * 4;
    const float*    xsrc = x  + (size_t)rb * K + k0 + c16 * 4;

    uint4 wreg[8], xreg[4];

    auto ldg = [&](int it) {
        const int kc = it * KC;
#pragma unroll
        for (int p = 0; p < 8; ++p)                  // weights: rows rb + p*8 (0..63)
            wreg[p] = *reinterpret_cast<const uint4*>(wsrc + (size_t)(p * 8) * K + kc);
#pragma unroll
        for (int p = 0; p < 4; ++p)                  // x: rows rb + p*8 (0..31)
            xreg[p] = *reinterpret_cast<const uint4*>(
                reinterpret_cast<const uint32_t*>(xsrc) + (size_t)(p * 8) * K + kc);
    };

    auto sts = [&](int buf) {
        __half* wt = smw[buf];
        __half* xt = wt + WT_HALVES;
#pragma unroll
        for (int p = 0; p < 8; ++p) {
            float f0, f1, f2, f3;
            if (mode == 0) {
                f0 = (float)(int)wreg[p].x; f1 = (float)(int)wreg[p].y;
                f2 = (float)(int)wreg[p].z; f3 = (float)(int)wreg[p].w;
            } else {
                f0 = __uint_as_float(wreg[p].x); f1 = __uint_as_float(wreg[p].y);
                f2 = __uint_as_float(wreg[p].z); f3 = __uint_as_float(wreg[p].w);
            }
            *reinterpret_cast<uint2*>(wt + (rb + p * 8) * WTS + c16 * 4) =
                make_uint2(h2_u32(__floats2half2_rn(f0, f1)),
                           h2_u32(__floats2half2_rn(f2, f3)));
        }
#pragma unroll
        for (int p = 0; p < 4; ++p) {
            float f0 = __uint_as_float(xreg[p].x), f1 = __uint_as_float(xreg[p].y);
            float f2 = __uint_as_float(xreg[p].z), f3 = __uint_as_float(xreg[p].w);
            *reinterpret_cast<uint2*>(xt + (rb + p * 8) * WTS + c16 * 4) =
                make_uint2(h2_u32(__floats2half2_rn(f0, f1)),
                           h2_u32(__floats2half2_rn(f2, f3)));
        }
    };

    // ldmatrix lane->address maps (byte offsets within a buffer)
    const int rowA  = ((lane >> 3) & 1) * 8 + (lane & 7);
    const int colA  = (lane >> 4) * 8;
    const int laneB = lane & 15;
    const int rowB  = laneB & 7;
    const int colB  = (laneB >> 3) * 8;
    const uint32_t b0u = (uint32_t)__cvta_generic_to_shared(&smw[0][0]);
    const uint32_t b1u = (uint32_t)__cvta_generic_to_shared(&smw[1][0]);
    const uint32_t aoff0 = (uint32_t)(WT_HALVES + (0  + rowA) * WTS + colA) * 2;
    const uint32_t aoff1 = (uint32_t)(WT_HALVES + (16 + rowA) * WTS + colA) * 2;
    const uint32_t boff0 = (uint32_t)((wn * 16 + 0 + rowB) * WTS + colB) * 2;
    const uint32_t boff1 = (uint32_t)((wn * 16 + 8 + rowB) * WTS + colB) * 2;

    float acc[2][2][4];
#pragma unroll
    for (int i = 0; i < 2; ++i)
#pragma unroll
        for (int j = 0; j < 2; ++j)
#pragma unroll
            for (int e = 0; e < 4; ++e) acc[i][j][e] = 0.f;

    auto compute = [&](uint32_t base) {
#pragma unroll
        for (int s = 0; s < 4; ++s) {                // full KC=64 per warp
            const uint32_t koff = (uint32_t)(s * 16) * 2;
            uint32_t a0[4], a1[4], bf0[2], bf1[2];
            ldsm4(a0, base + aoff0 + koff);
            ldsm4(a1, base + aoff1 + koff);
            ldsm2(bf0, base + boff0 + koff);
            ldsm2(bf1, base + boff1 + koff);
            mma16816(acc[0][0], a0, bf0);
            mma16816(acc[0][1], a0, bf1);
            mma16816(acc[1][0], a1, bf0);
            mma16816(acc[1][1], a1, bf1);
        }
    };

    // ---- mainloop (r3 cadence) ----
    ldg(0);
    sts(0);
    __syncthreads();

    for (int it = 0; it < NITER; ++it) {
        const bool more = (it + 1 < NITER);
        if (more) ldg(it + 1);
        compute((it & 1) ? b1u : b0u);
        if (more) sts((it + 1) & 1);
        __syncthreads();
    }

    // ---- write raw fp32 partials to this split's slice ----
    float* dst = &g_partial[spl][0][0];
    const int gm = lane >> 2;
    const int gn = (lane & 3) * 2;
#pragma unroll
    for (int nt = 0; nt < 2; ++nt) {
        const int o = o0 + wn * 16 + nt * 8 + gn;
#pragma unroll
        for (int mt = 0; mt < 2; ++mt) {
            const float* c = acc[mt][nt];
            const int r0 = mt * 16 + gm;
            *reinterpret_cast<float2*>(dst + (size_t)r0 * N + o)       = make_float2(c[0], c[1]);
            *reinterpret_cast<float2*>(dst + (size_t)(r0 + 8) * N + o) = make_float2(c[2], c[3]);
        }
    }
}

__global__ void __launch_bounds__(256)
qlinear_finalize(const float* __restrict__ scales, const float* __restrict__ bias,
                 float* __restrict__ out)
{
    const int o = blockIdx.x * 256 + threadIdx.x;   // 43*256 = 11008 exactly
    const int t = blockIdx.y;
    float s = g_partial[0][t][o] + g_partial[1][t][o]
            + g_partial[2][t][o] + g_partial[3][t][o];
    out[(size_t)t * N + o] = __half2float(__float2half_rn(s * scales[o] + bias[o]));
}

} // anonymous namespace

extern "C" void kernel_launch(void* const* d_in, const int* in_sizes, int n_in,
                              void* d_out, int out_size) {
    const float*    x  = reinterpret_cast<const float*>(d_in[0]);
    const uint32_t* qw = reinterpret_cast<const uint32_t*>(d_in[1]);
    const float*    sc = reinterpret_cast<const float*>(d_in[2]);
    const float*    bi = reinterpret_cast<const float*>(d_in[3]);
    float*          o  = reinterpret_cast<float*>(d_out);

    qlinear_main<<<dim3(N / NT, NSPLIT), 128>>>(x, qw);
    qlinear_finalize<<<dim3(N / 256, M), 256>>>(sc, bi, o);
}